// round 3
// baseline (speedup 1.0000x reference)
#include <cuda_runtime.h>
#include <stdint.h>

#define NFRAMES   256
#define VOX       32768              // 32*32*32
#define VOX4      (VOX / 4)          // 8192 float4 per channel per frame
#define KCAP      512
#define MAXEV     100
#define NT1       256                // threads, streaming kernel
#define NT2       256                // threads, NMS kernel
#define GRID1     2960               // 20 CTAs/SM on 148 SMs
#define HASH_SZ   1024
#define HASH_MASK 1023
#define HEMPTY    0xFFFFFFFFu

#define ST_UNDEC 0
#define ST_KEPT  1
#define ST_SUPP  2

// Global scratch (allowed: __device__ arrays). Zero-initialized at module load;
// nms kernel resets counts after use so every replay starts clean.
__device__ unsigned long long g_keys[NFRAMES * KCAP];
__device__ int                g_count[NFRAMES];

// ---------------- Kernel 1: zero output + compact nonzero energy ----------------
__global__ __launch_bounds__(NT1)
void zero_compact_kernel(const float* __restrict__ in, float* __restrict__ out)
{
    const float4 z4 = make_float4(0.f, 0.f, 0.f, 0.f);
    const float4* in4 = (const float4*)in;
    float4* out4 = (float4*)out;

    const int total = NFRAMES * VOX4;      // 2M float4 (energy view)
    const int stride = gridDim.x * NT1;

    for (int idx = blockIdx.x * NT1 + threadIdx.x; idx < total; idx += stride) {
        const int frame = idx >> 13;               // / VOX4
        const int off   = idx & (VOX4 - 1);
        const int base4 = frame * (2 * VOX4);      // frame start in float4 units

        // zero both channels at this offset
        out4[base4 + off]        = z4;
        out4[base4 + VOX4 + off] = z4;

        // read energy, compact nonzeros
        float4 v = in4[base4 + off];
        float vv[4] = { v.x, v.y, v.z, v.w };
        const int voxbase = off * 4;
        #pragma unroll
        for (int c = 0; c < 4; c++) {
            if (vv[c] > 0.0f) {
                int p = atomicAdd(&g_count[frame], 1);
                if (p < KCAP) {
                    unsigned int fb  = __float_as_uint(vv[c]);
                    unsigned int vox = (unsigned int)(voxbase + c);
                    // desc by value, tie -> asc voxel index (matches lax.top_k)
                    g_keys[frame * KCAP + p] =
                        ((unsigned long long)fb << 32) | (unsigned int)(~vox);
                }
            }
        }
    }
}

// ---------------- Kernel 2: per-frame sort + NMS + scatter ----------------
__global__ __launch_bounds__(NT2)
void nms_scatter_kernel(const float* __restrict__ in, float* __restrict__ out)
{
    const int frame = blockIdx.x;
    const float* fin  = in  + (size_t)frame * 2 * VOX;
    float*       fout = out + (size_t)frame * 2 * VOX;
    const int tid = threadIdx.x;

    __shared__ unsigned long long skey[KCAP];
    __shared__ unsigned int       htab[HASH_SZ];
    __shared__ unsigned char      status[KCAP];
    __shared__ int changed;
    __shared__ int totKept;

    int n = g_count[frame];
    if (n > KCAP) n = KCAP;

    if (n == 0) {
        // empty frame passes through unchanged (overwrite the zeros)
        const float4* s = (const float4*)fin;
        float4*       d = (float4*)fout;
        for (int i = tid; i < 2 * VOX4; i += NT2) d[i] = s[i];
        if (tid == 0) g_count[frame] = 0;
        return;
    }

    if (tid == 0) { totKept = 0; g_count[frame] = 0; }   // reset for next replay
    for (int i = tid; i < HASH_SZ; i += NT2) htab[i] = HEMPTY;
    #pragma unroll
    for (int ii = 0; ii < KCAP / NT2; ii++) {
        int i = tid + ii * NT2;
        skey[i]   = (i < n) ? g_keys[frame * KCAP + i] : 0ULL;
        status[i] = ST_SUPP;
    }
    __syncthreads();

    // bitonic sort, descending (512 keys, 2 per thread)
    for (int k = 2; k <= KCAP; k <<= 1) {
        for (int j = k >> 1; j > 0; j >>= 1) {
            #pragma unroll
            for (int ii = 0; ii < KCAP / NT2; ii++) {
                int i = tid + ii * NT2;
                int ixj = i ^ j;
                if (ixj > i) {
                    unsigned long long a = skey[i], b = skey[ixj];
                    bool desc = ((i & k) == 0);
                    if (desc ? (a < b) : (a > b)) { skey[i] = b; skey[ixj] = a; }
                }
            }
            __syncthreads();
        }
    }

    // hash insert: voxel -> rank
    for (int r = tid; r < n; r += NT2) {
        unsigned int vox = ~((unsigned int)skey[r]);
        unsigned int h = (vox * 2654435761u) >> 22;
        unsigned int entry = (vox << 9) | (unsigned int)r;
        while (true) {
            unsigned int prev = atomicCAS(&htab[h], HEMPTY, entry);
            if (prev == HEMPTY) break;
            h = (h + 1) & HASH_MASK;
        }
        status[r] = ST_UNDEC;
    }
    __syncthreads();

    // NMS fixpoint (dist<2.0 on int coords == 26-neighborhood); unique fixpoint = greedy
    for (int round = 0; round < KCAP; round++) {
        if (tid == 0) changed = 0;
        __syncthreads();

        for (int r = tid; r < n; r += NT2) {
            if (status[r] != ST_UNDEC) continue;
            unsigned int vox = ~((unsigned int)skey[r]);
            int z = vox >> 10, y = (vox >> 5) & 31, x = vox & 31;

            bool anyKept = false, allDec = true;
            #pragma unroll
            for (int dz = -1; dz <= 1; dz++)
            #pragma unroll
            for (int dy = -1; dy <= 1; dy++)
            #pragma unroll
            for (int dx = -1; dx <= 1; dx++) {
                if (dz == 0 && dy == 0 && dx == 0) continue;
                int nz = z + dz, ny = y + dy, nx = x + dx;
                if ((unsigned)nz >= 32u || (unsigned)ny >= 32u || (unsigned)nx >= 32u) continue;
                unsigned int nv = ((unsigned)nz << 10) | ((unsigned)ny << 5) | (unsigned)nx;
                unsigned int h = (nv * 2654435761u) >> 22;
                while (true) {
                    unsigned int e = htab[h];
                    if (e == HEMPTY) break;
                    if ((e >> 9) == nv) {
                        int q = (int)(e & 511u);
                        if (q < r) {
                            unsigned char sq = status[q];
                            if (sq == ST_KEPT) anyKept = true;
                            else if (sq == ST_UNDEC) allDec = false;
                        }
                        break;
                    }
                    h = (h + 1) & HASH_MASK;
                }
            }
            if (anyKept)     { status[r] = ST_SUPP; changed = 1; }
            else if (allDec) { status[r] = ST_KEPT; changed = 1; }
        }
        __syncthreads();
        if (changed == 0) break;
        __syncthreads();
    }

    // count kept -> MAX_EVENTS rank cut
    {
        int local = 0;
        for (int r = tid; r < n; r += NT2)
            if (status[r] == ST_KEPT) local++;
        if (local) atomicAdd(&totKept, local);
    }
    __syncthreads();
    const bool cut = (totKept > MAXEV);

    // scatter kept points over the pre-zeroed output
    for (int r = tid; r < n; r += NT2) {
        if (status[r] == ST_KEPT && (!cut || r < MAXEV)) {
            unsigned long long key = skey[r];
            unsigned int vox = ~((unsigned int)key);
            fout[vox]       = __uint_as_float((unsigned int)(key >> 32));
            fout[VOX + vox] = fin[VOX + vox];
        }
    }
}

extern "C" void kernel_launch(void* const* d_in, const int* in_sizes, int n_in,
                              void* d_out, int out_size)
{
    (void)in_sizes; (void)n_in; (void)out_size;
    const float* x   = (const float*)d_in[0];
    float*       out = (float*)d_out;
    zero_compact_kernel<<<GRID1, NT1>>>(x, out);
    nms_scatter_kernel<<<NFRAMES, NT2>>>(x, out);
}

// round 4
// speedup vs baseline: 1.3492x; 1.3492x over previous
#include <cuda_runtime.h>
#include <stdint.h>

#define NFRAMES   256
#define VOX       32768
#define VOX4      (VOX / 4)          // 8192
#define KCAP      512
#define MAXEV     100
#define NT1       256
#define GRID1     2048               // 2048*256 threads * 4 slots = 2,097,152 exactly
#define NT2       256
#define HASH_SZ   1024
#define HASH_MASK 1023
#define HEMPTY    0xFFFFFFFFu
#define NBMAX     8
#define NB_OVF    0x80

#define ST_UNDEC 0
#define ST_KEPT  1
#define ST_SUPP  2

__device__ unsigned long long g_keys[NFRAMES * KCAP];
__device__ int                g_count[NFRAMES];

// ---------------- Kernel 1: zero output + warp-aggregated compaction ----------------
__global__ __launch_bounds__(NT1)
void zero_compact_kernel(const float* __restrict__ in, float* __restrict__ out)
{
    const float4 z4 = make_float4(0.f, 0.f, 0.f, 0.f);
    const float4* in4 = (const float4*)in;
    float4* out4 = (float4*)out;

    const int total  = NFRAMES * VOX4;           // 2,097,152
    const int stride = GRID1 * NT1;
    const int lane   = threadIdx.x & 31;
    const unsigned FULL = 0xFFFFFFFFu;

    for (int idx = blockIdx.x * NT1 + threadIdx.x; idx < total; idx += stride) {
        const int frame = idx >> 13;             // / VOX4  (warp never crosses a frame)
        const int off   = idx & (VOX4 - 1);
        const int base4 = frame << 14;           // * 2*VOX4

        out4[base4 + off]        = z4;
        out4[base4 + VOX4 + off] = z4;

        float4 v = in4[base4 + off];
        unsigned m0 = __ballot_sync(FULL, v.x > 0.0f);
        unsigned m1 = __ballot_sync(FULL, v.y > 0.0f);
        unsigned m2 = __ballot_sync(FULL, v.z > 0.0f);
        unsigned m3 = __ballot_sync(FULL, v.w > 0.0f);
        unsigned any = m0 | m1 | m2 | m3;
        if (any == 0) continue;

        int tot = __popc(m0) + __popc(m1) + __popc(m2) + __popc(m3);
        int base;
        if (lane == 0) base = atomicAdd(&g_count[frame], tot);
        base = __shfl_sync(FULL, base, 0);

        const unsigned lt = (1u << lane) - 1u;
        int pre = __popc(m0 & lt) + __popc(m1 & lt) + __popc(m2 & lt) + __popc(m3 & lt);
        const unsigned mybit = 1u << lane;
        const int voxbase = off * 4;
        float vv[4] = { v.x, v.y, v.z, v.w };
        unsigned mm[4] = { m0, m1, m2, m3 };
        int sub = 0;
        #pragma unroll
        for (int c = 0; c < 4; c++) {
            if (mm[c] & mybit) {
                int p = base + pre + sub;
                if (p < KCAP) {
                    unsigned int fb  = __float_as_uint(vv[c]);
                    unsigned int vox = (unsigned int)(voxbase + c);
                    // desc by value, tie -> asc voxel index (matches lax.top_k)
                    g_keys[frame * KCAP + p] =
                        ((unsigned long long)fb << 32) | (unsigned int)(~vox);
                }
                sub++;
            }
        }
    }
}

// ---------------- Kernel 2: rank-count + adjacency + fixpoint NMS + scatter ----------------
__global__ __launch_bounds__(NT2)
void nms_scatter_kernel(const float* __restrict__ in, float* __restrict__ out)
{
    const int frame = blockIdx.x;
    const float* fin  = in  + (size_t)frame * 2 * VOX;
    float*       fout = out + (size_t)frame * 2 * VOX;
    const int tid = threadIdx.x;

    __shared__ unsigned long long skey[KCAP];    // unsorted keys
    __shared__ unsigned long long rkey[KCAP];    // rank-ordered keys
    __shared__ unsigned int       htab[HASH_SZ]; // vox -> rank
    __shared__ unsigned short     nbr[KCAP * NBMAX];
    __shared__ unsigned char      nbrcnt[KCAP];
    __shared__ unsigned char      status[KCAP];
    __shared__ int changed;

    int n = g_count[frame];
    if (n > KCAP) n = KCAP;

    if (n == 0) {
        const float4* s = (const float4*)fin;
        float4*       d = (float4*)fout;
        for (int i = tid; i < 2 * VOX4; i += NT2) d[i] = s[i];
        if (tid == 0) g_count[frame] = 0;
        return;
    }
    if (tid == 0) g_count[frame] = 0;            // reset for next graph replay

    // init + load
    for (int i = tid; i < HASH_SZ; i += NT2) htab[i] = HEMPTY;
    #pragma unroll
    for (int ii = 0; ii < KCAP / NT2; ii++) {
        int i = tid + ii * NT2;
        skey[i]   = (i < n) ? g_keys[frame * KCAP + i] : 0ULL;
        status[i] = ST_SUPP;
    }
    __syncthreads();

    // ---- rank by counting (keys unique: voxel in low bits) ----
    {
        int i0 = tid, i1 = tid + NT2;
        unsigned long long k0 = skey[i0];
        unsigned long long k1 = (i1 < KCAP) ? skey[i1] : 0ULL;
        int r0 = 0, r1 = 0;
        for (int j = 0; j < n; j++) {
            unsigned long long kj = skey[j];     // broadcast
            r0 += (kj > k0);
            r1 += (kj > k1);
        }
        if (i0 < n) {
            rkey[r0] = k0;
            status[r0] = ST_UNDEC;
            unsigned int vox = ~((unsigned int)k0);
            unsigned int h = (vox * 2654435761u) >> 22;
            unsigned int entry = (vox << 9) | (unsigned int)r0;
            while (atomicCAS(&htab[h], HEMPTY, entry) != HEMPTY) h = (h + 1) & HASH_MASK;
        }
        if (i1 < n) {
            rkey[r1] = k1;
            status[r1] = ST_UNDEC;
            unsigned int vox = ~((unsigned int)k1);
            unsigned int h = (vox * 2654435761u) >> 22;
            unsigned int entry = (vox << 9) | (unsigned int)r1;
            while (atomicCAS(&htab[h], HEMPTY, entry) != HEMPTY) h = (h + 1) & HASH_MASK;
        }
    }
    __syncthreads();

    // ---- adjacency: earlier-ranked neighbors in the 26-neighborhood ----
    for (int r = tid; r < n; r += NT2) {
        unsigned int vox = ~((unsigned int)rkey[r]);
        int z = vox >> 10, y = (vox >> 5) & 31, x = vox & 31;
        int cnt = 0; bool ovf = false;
        #pragma unroll
        for (int dz = -1; dz <= 1; dz++)
        #pragma unroll
        for (int dy = -1; dy <= 1; dy++)
        #pragma unroll
        for (int dx = -1; dx <= 1; dx++) {
            if (dz == 0 && dy == 0 && dx == 0) continue;
            int nz = z + dz, ny = y + dy, nx = x + dx;
            if ((unsigned)nz >= 32u || (unsigned)ny >= 32u || (unsigned)nx >= 32u) continue;
            unsigned int nv = ((unsigned)nz << 10) | ((unsigned)ny << 5) | (unsigned)nx;
            unsigned int h = (nv * 2654435761u) >> 22;
            while (true) {
                unsigned int e = htab[h];
                if (e == HEMPTY) break;
                if ((e >> 9) == nv) {
                    int q = (int)(e & 511u);
                    if (q < r) {
                        if (cnt < NBMAX) nbr[r * NBMAX + cnt] = (unsigned short)q;
                        else ovf = true;
                        cnt++;
                    }
                    break;
                }
                h = (h + 1) & HASH_MASK;
            }
        }
        nbrcnt[r] = ovf ? (unsigned char)(NB_OVF | NBMAX) : (unsigned char)cnt;
    }
    __syncthreads();

    // ---- fixpoint NMS (unique fixpoint == sequential greedy) ----
    for (int round = 0; round < KCAP; round++) {
        if (tid == 0) changed = 0;
        __syncthreads();

        for (int r = tid; r < n; r += NT2) {
            if (status[r] != ST_UNDEC) continue;
            unsigned char nc = nbrcnt[r];
            bool anyKept = false, allDec = true;
            if (nc & NB_OVF) {
                // rare overflow: full re-probe
                unsigned int vox = ~((unsigned int)rkey[r]);
                int z = vox >> 10, y = (vox >> 5) & 31, x = vox & 31;
                for (int dz = -1; dz <= 1; dz++)
                for (int dy = -1; dy <= 1; dy++)
                for (int dx = -1; dx <= 1; dx++) {
                    if (dz == 0 && dy == 0 && dx == 0) continue;
                    int nz = z + dz, ny = y + dy, nx = x + dx;
                    if ((unsigned)nz >= 32u || (unsigned)ny >= 32u || (unsigned)nx >= 32u) continue;
                    unsigned int nv = ((unsigned)nz << 10) | ((unsigned)ny << 5) | (unsigned)nx;
                    unsigned int h = (nv * 2654435761u) >> 22;
                    while (true) {
                        unsigned int e = htab[h];
                        if (e == HEMPTY) break;
                        if ((e >> 9) == nv) {
                            int q = (int)(e & 511u);
                            if (q < r) {
                                unsigned char sq = status[q];
                                if (sq == ST_KEPT) anyKept = true;
                                else if (sq == ST_UNDEC) allDec = false;
                            }
                            break;
                        }
                        h = (h + 1) & HASH_MASK;
                    }
                }
            } else {
                #pragma unroll 4
                for (int k = 0; k < (int)nc; k++) {
                    unsigned char sq = status[nbr[r * NBMAX + k]];
                    if (sq == ST_KEPT) anyKept = true;
                    else if (sq == ST_UNDEC) allDec = false;
                }
            }
            if (anyKept)     { status[r] = ST_SUPP; changed = 1; }
            else if (allDec) { status[r] = ST_KEPT; changed = 1; }
        }
        __syncthreads();
        if (changed == 0) break;
        __syncthreads();
    }

    // ---- kept count (barrier-fused) + MAX_EVENTS rank cut ----
    int c0 = __syncthreads_count(tid       < n && status[tid]       == ST_KEPT);
    int c1 = __syncthreads_count(tid + NT2 < n && status[tid + NT2] == ST_KEPT);
    const bool cut = (c0 + c1 > MAXEV);

    // ---- scatter kept points over pre-zeroed output ----
    for (int r = tid; r < n; r += NT2) {
        if (status[r] == ST_KEPT && (!cut || r < MAXEV)) {
            unsigned long long key = rkey[r];
            unsigned int vox = ~((unsigned int)key);
            fout[vox]       = __uint_as_float((unsigned int)(key >> 32));
            fout[VOX + vox] = fin[VOX + vox];
        }
    }
}

extern "C" void kernel_launch(void* const* d_in, const int* in_sizes, int n_in,
                              void* d_out, int out_size)
{
    (void)in_sizes; (void)n_in; (void)out_size;
    const float* x   = (const float*)d_in[0];
    float*       out = (float*)d_out;
    zero_compact_kernel<<<GRID1, NT1>>>(x, out);
    nms_scatter_kernel<<<NFRAMES, NT2>>>(x, out);
}